// round 15
// baseline (speedup 1.0000x reference)
#include <cuda_runtime.h>
#include <cuda_bf16.h>
#include <cstdint>

// Problem constants
#define B_   64
#define L_   4096
#define KD_  128
#define H_   4
#define OUT_ 256

#define CHUNKS 16                // L-chunks per batch (pass 1)
#define WARPS  4                 // warps per block in pass 1 (128 threads)
#define ROWS_PER_WARP (L_ / CHUNKS / WARPS)   // 64 rows per warp
#define NBLK1 (B_ * CHUNKS)      // 1024

typedef unsigned long long u64;

// Deterministic scratch (no device allocation allowed)
__device__ float g_pacc[NBLK1][KD_ * H_];   // 1024 x 512 f32 = 2 MB
__device__ float g_pZ[NBLK1][H_];
__device__ float g_pooled[B_][KD_ * H_];    // normalized pooled vectors

__device__ __forceinline__ float warp_sum32(float v) {
#pragma unroll
    for (int off = 16; off >= 1; off >>= 1)
        v += __shfl_xor_sync(0xffffffffu, v, off);
    return v;
}

__device__ __forceinline__ uint32_t smem_u32(const void* p) {
    uint32_t a;
    asm("{ .reg .u64 t; cvta.to.shared.u64 t, %1; cvt.u32.u64 %0, t; }"
        : "=r"(a) : "l"(p));
    return a;
}

// Volatile LDS.128: guaranteed in-loop (prevents hoisting q back into regs).
__device__ __forceinline__ float4 lds128v(uint32_t addr) {
    float4 r;
    asm volatile("ld.shared.v4.f32 {%0,%1,%2,%3}, [%4];"
                 : "=f"(r.x), "=f"(r.y), "=f"(r.z), "=f"(r.w) : "r"(addr));
    return r;
}

#define PACK2(d, lo, hi)   asm("mov.b64 %0, {%1, %2};" : "=l"(d) : "f"(lo), "f"(hi))
#define UNPACK2(lo, hi, s) asm("mov.b64 {%0, %1}, %2;" : "=f"(lo), "=f"(hi) : "l"(s))
#define FMA2(d, a, b)      asm("fma.rn.f32x2 %0, %1, %2, %0;" : "+l"(d) : "l"(a), "l"(b))

// 8-value butterfly transpose-reduce. In: wv[0..7] per lane. Out: return on
// lane l == full 32-lane sum of value (l & 7). (R10/R13-proven.)
__device__ __forceinline__ float butterfly8(float wv[8], int lane) {
#pragma unroll
    for (int step = 0; step < 3; step++) {
        const int off = 4 >> step;
        const bool up = (lane & off) != 0;
#pragma unroll
        for (int i = 0; i < 4; i++) {
            if (i < (4 >> step)) {
                const float send = up ? wv[i] : wv[i + (4 >> step)];
                const float recv = __shfl_xor_sync(0xffffffffu, send, off);
                wv[i] = (up ? wv[i + (4 >> step)] : wv[i]) + recv;
            }
        }
    }
    float s = wv[0];
    s += __shfl_xor_sync(0xffffffffu, s, 8);
    s += __shfl_xor_sync(0xffffffffu, s, 16);
    return s;
}

// ---------------------------------------------------------------------------
// Pass 1 (R14-measured best, ~18.5us): row-list compaction, q in smem via
// volatile LDS (regs under the 64 cap naturally), xv in registers, dual
// butterfly8, FFMA2 accumulate with duplicated (e,e) weights in smem.
// exp(-1e9)==0 in fp32 => skipping masked rows is exact; |score|<~4 => no
// max subtraction needed.
// ---------------------------------------------------------------------------
__global__ void __launch_bounds__(128, 8)
pool_pass1(const float* __restrict__ x,
           const int* __restrict__ mask,   // bool coerced to int32 by harness
           const float* __restrict__ q)
{
    const int blk  = blockIdx.x;
    const int b    = blk / CHUNKS;
    const int c    = blk % CHUNKS;
    const int w    = threadIdx.x >> 5;
    const int lane = threadIdx.x & 31;

    __shared__ float4 qS[H_][32];            // query chunks, lane-strided
    __shared__ __align__(16) u64 wdupS[WARPS][2][16]; // duplicated weights, dbl-buf
    __shared__ float  sAcc[WARPS][KD_ * H_];
    __shared__ float  sZ[WARPS][H_];
    __shared__ int    rowsS[WARPS][ROWS_PER_WARP + 4];

    // qS[h][lane] = floats [lane*4, lane*4+4) of head h's query (w == h)
    qS[w][lane] = *reinterpret_cast<const float4*>(q + w * KD_ + lane * 4);

    // ---- build this warp's live-row list (once) ----
    const int l0 = c * (L_ / CHUNKS) + w * ROWS_PER_WARP;
    const int* mb = mask + (size_t)b * L_ + l0;
    int cnt = 0;
#pragma unroll
    for (int half = 0; half < 2; half++) {
        const unsigned mm = __ballot_sync(0xffffffffu, mb[half * 32 + lane] != 0);
        const int rank = __popc(mm & ((1u << lane) - 1));
        if ((mm >> lane) & 1u) rowsS[w][cnt + rank] = half * 32 + lane;
        cnt += __popc(mm);
    }
    if (lane < 4) rowsS[w][cnt + lane] = 0;   // pad (zero-weighted later)
    __syncthreads();                          // qS visible to all warps

    // accP[jp][h] = (acc[2jp][h], acc[2jp+1][h])
    u64 accP[2][H_];
    {
        const float z = 0.0f;
#pragma unroll
        for (int jp = 0; jp < 2; jp++)
#pragma unroll
            for (int h = 0; h < H_; h++) PACK2(accP[jp][h], z, z);
    }
    float zaccA = 0.0f, zaccB = 0.0f;

    const char* baseL = (const char*)(x + (size_t)b * L_ * KD_ + (size_t)l0 * KD_)
                        + lane * 16;
    const uint32_t qAddr = smem_u32(&qS[0][lane]);   // +512*h per head
    const int myrow = (lane & 7) >> 1;

    int pb = 0;
#pragma unroll 1
    for (int base = 0; base < cnt; base += 4) {
        const float keep = (base + myrow < cnt) ? 1.0f : 0.0f;

        int r[4];
#pragma unroll
        for (int i = 0; i < 4; i++) r[i] = rowsS[w][base + i];   // LDS broadcast

        float4 xv[4];
#pragma unroll
        for (int i = 0; i < 4; i++)
            xv[i] = *reinterpret_cast<const float4*>(baseL + ((unsigned)r[i] << 9));

        // ---- batch A: heads 0,1 -> wv[row*2 + hh] ----
        float wv[8];
        {
            const float4 qa = lds128v(qAddr);
            const float4 qb = lds128v(qAddr + 512);
#pragma unroll
            for (int i = 0; i < 4; i++) {
                wv[i * 2 + 0] = xv[i].x * qa.x + xv[i].y * qa.y
                              + xv[i].z * qa.z + xv[i].w * qa.w;
                wv[i * 2 + 1] = xv[i].x * qb.x + xv[i].y * qb.y
                              + xv[i].z * qb.z + xv[i].w * qb.w;
            }
        }
        float eA = __expf(butterfly8(wv, lane)) * keep;

        // ---- batch B: heads 2,3 ----
        {
            const float4 qc = lds128v(qAddr + 1024);
            const float4 qd = lds128v(qAddr + 1536);
#pragma unroll
            for (int i = 0; i < 4; i++) {
                wv[i * 2 + 0] = xv[i].x * qc.x + xv[i].y * qc.y
                              + xv[i].z * qc.z + xv[i].w * qc.w;
                wv[i * 2 + 1] = xv[i].x * qd.x + xv[i].y * qd.y
                              + xv[i].z * qd.z + xv[i].w * qd.w;
            }
        }
        float eB = __expf(butterfly8(wv, lane)) * keep;

        // ---- duplicated weight store: lanes 0..7, 2 STS.64 each ----
        if (lane < 8) {
            const int row = lane >> 1, hh = lane & 1;
            u64 dA, dB;
            PACK2(dA, eA, eA);
            PACK2(dB, eB, eB);
            wdupS[w][pb][row * 4 + hh]     = dA;   // heads 0,1
            wdupS[w][pb][row * 4 + 2 + hh] = dB;   // heads 2,3
        } else {
            eA = 0.0f; eB = 0.0f;
        }
        __syncwarp();
        zaccA += eA;                    // Z[lane&1]     partial
        zaccB += eB;                    // Z[2+(lane&1)] partial

        // ---- accumulate 4 rows: 2 LDS.128 + 2 packs + 8 FFMA2 per row ----
#pragma unroll
        for (int i = 0; i < 4; i++) {
            const ulonglong2 wd01 = *reinterpret_cast<const ulonglong2*>(&wdupS[w][pb][i * 4]);
            const ulonglong2 wd23 = *reinterpret_cast<const ulonglong2*>(&wdupS[w][pb][i * 4 + 2]);
            u64 x01, x23;
            PACK2(x01, xv[i].x, xv[i].y);
            PACK2(x23, xv[i].z, xv[i].w);
            FMA2(accP[0][0], x01, wd01.x); FMA2(accP[1][0], x23, wd01.x);
            FMA2(accP[0][1], x01, wd01.y); FMA2(accP[1][1], x23, wd01.y);
            FMA2(accP[0][2], x01, wd23.x); FMA2(accP[1][2], x23, wd23.x);
            FMA2(accP[0][3], x01, wd23.y); FMA2(accP[1][3], x23, wd23.y);
        }
        pb ^= 1;                       // next iter writes other buffer; its
                                       // syncwarp fences reuse of this one.
    }

    // Z reduce: same-parity lanes -> lanes 0,1 hold (Z0,Z1) and (Z2,Z3)
    float zA = zaccA, zB = zaccB;
#pragma unroll
    for (int off = 16; off >= 2; off >>= 1) {
        zA += __shfl_xor_sync(0xffffffffu, zA, off);
        zB += __shfl_xor_sync(0xffffffffu, zB, off);
    }

    // ---- block-level deterministic reduce ----
#pragma unroll
    for (int h = 0; h < H_; h++) {
        float a0, a1, a2, a3;
        UNPACK2(a0, a1, accP[0][h]);   // j = 0, 1
        UNPACK2(a2, a3, accP[1][h]);   // j = 2, 3
        sAcc[w][(lane * 4 + 0) * H_ + h] = a0;
        sAcc[w][(lane * 4 + 1) * H_ + h] = a1;
        sAcc[w][(lane * 4 + 2) * H_ + h] = a2;
        sAcc[w][(lane * 4 + 3) * H_ + h] = a3;
    }
    if (lane < 2) {
        sZ[w][lane]     = zA;
        sZ[w][2 + lane] = zB;
    }
    __syncthreads();

    for (int idx = threadIdx.x; idx < KD_ * H_; idx += 128) {
        float vv = 0.f;
#pragma unroll
        for (int ww = 0; ww < WARPS; ww++) vv += sAcc[ww][idx];
        g_pacc[blk][idx] = vv;
    }
    if (threadIdx.x < H_) {
        float vv = 0.f;
#pragma unroll
        for (int ww = 0; ww < WARPS; ww++) vv += sZ[ww][threadIdx.x];
        g_pZ[blk][threadIdx.x] = vv;
    }
}

// ---------------------------------------------------------------------------
// Pass 2a (split, R13-proven): combine chunk partials + normalize -> g_pooled.
// 64 blocks x 512 threads: one thread per pooled element, 16 independent loads.
// ---------------------------------------------------------------------------
__global__ void __launch_bounds__(512, 2)
pool_combine()
{
    const int b   = blockIdx.x;
    const int tid = threadIdx.x;
    __shared__ float Zs[H_];

    if (tid < H_) {
        float vv = 0.f;
#pragma unroll
        for (int c = 0; c < CHUNKS; c++) vv += g_pZ[b * CHUNKS + c][tid];
        Zs[tid] = vv;
    }
    float vv = 0.f;
#pragma unroll
    for (int c = 0; c < CHUNKS; c++) vv += g_pacc[b * CHUNKS + c][tid];
    __syncthreads();
    g_pooled[b][tid] = vv / Zs[tid & (H_ - 1)];
}

// ---------------------------------------------------------------------------
// Pass 2b (split, R13-proven): out = relu(pooled @ W^T + b + relu(emb[num])).
// Grid = B * 8 (batch x 32-output group); warp computes 4 outputs.
// ---------------------------------------------------------------------------
__global__ void __launch_bounds__(256, 4)
pool_gemv(const float* __restrict__ W,
          const float* __restrict__ bias,
          const float* __restrict__ emb,
          const int* __restrict__ num,
          float* __restrict__ out)
{
    const int b    = blockIdx.x >> 3;
    const int og   = blockIdx.x & 7;
    const int tid  = threadIdx.x;
    const int wrp  = tid >> 5;
    const int lane = tid & 31;
    const int o0   = og * 32 + wrp * 4;

    __shared__ float pooled[KD_ * H_];
    for (int idx = tid; idx < (KD_ * H_) / 4; idx += 256)
        reinterpret_cast<float4*>(pooled)[idx] =
            reinterpret_cast<const float4*>(g_pooled[b])[idx];
    __syncthreads();

    float4 pv[4];
#pragma unroll
    for (int qi = 0; qi < 4; qi++)
        pv[qi] = *reinterpret_cast<const float4*>(&pooled[qi * 128 + lane * 4]);

    float a[4];
#pragma unroll
    for (int j = 0; j < 4; j++) {
        const float* Wr = W + (size_t)(o0 + j) * (KD_ * H_);
        float ssum = 0.f;
#pragma unroll
        for (int qi = 0; qi < 4; qi++) {
            const float4 wv = *reinterpret_cast<const float4*>(Wr + qi * 128 + lane * 4);
            ssum = fmaf(wv.x, pv[qi].x, fmaf(wv.y, pv[qi].y,
                   fmaf(wv.z, pv[qi].z, fmaf(wv.w, pv[qi].w, ssum))));
        }
        a[j] = warp_sum32(ssum);
    }

    if (lane == 0) {
        const int nb = num[b];
#pragma unroll
        for (int j = 0; j < 4; j++) {
            const int o = o0 + j;
            float vv = a[j] + bias[o] + fmaxf(emb[(size_t)nb * OUT_ + o], 0.f);
            out[(size_t)b * OUT_ + o] = fmaxf(vv, 0.f);
        }
    }
}

// ---------------------------------------------------------------------------
// Launch.  Inputs (metadata order): x, mask, num, queries, W, b, emb
// ---------------------------------------------------------------------------
extern "C" void kernel_launch(void* const* d_in, const int* in_sizes, int n_in,
                              void* d_out, int out_size)
{
    const float* x    = (const float*)d_in[0];
    const int*   mask = (const int*)d_in[1];     // bool -> int32 on upload
    const int*   num  = (const int*)d_in[2];
    const float* q    = (const float*)d_in[3];
    const float* W    = (const float*)d_in[4];
    const float* bias = (const float*)d_in[5];
    const float* emb  = (const float*)d_in[6];
    float*       out  = (float*)d_out;

    pool_pass1<<<NBLK1, 128>>>(x, mask, q);
    pool_combine<<<B_, 512>>>();
    pool_gemv<<<B_ * 8, 256>>>(W, bias, emb, num, out);
}

// round 16
// speedup vs baseline: 1.1098x; 1.1098x over previous
#include <cuda_runtime.h>
#include <cuda_bf16.h>
#include <cstdint>

// Problem constants
#define B_   64
#define L_   4096
#define KD_  128
#define H_   4
#define OUT_ 256

#define CHUNKS 16                // L-chunks per batch (pass 1)
#define WARPS  4                 // warps per block in pass 1 (128 threads)
#define ROWS_PER_WARP (L_ / CHUNKS / WARPS)   // 64 rows per warp
#define NBLK1 (B_ * CHUNKS)      // 1024

// Deterministic scratch (no device allocation allowed)
__device__ float g_pacc[NBLK1][KD_ * H_];   // 1024 x 512 f32 = 2 MB
__device__ float g_pZ[NBLK1][H_];
__device__ float g_pooled[B_][KD_ * H_];    // normalized pooled vectors
__device__ int   g_cnt[B_];                 // BSS-zeroed; each run restores 0

__device__ __forceinline__ float warp_sum32(float v) {
#pragma unroll
    for (int off = 16; off >= 1; off >>= 1)
        v += __shfl_xor_sync(0xffffffffu, v, off);
    return v;
}

__device__ __forceinline__ uint32_t smem_u32(const void* p) {
    uint32_t a;
    asm("{ .reg .u64 t; cvta.to.shared.u64 t, %1; cvt.u32.u64 %0, t; }"
        : "=r"(a) : "l"(p));
    return a;
}

// Volatile LDS.128: guaranteed in-loop (prevents hoisting q back into regs).
__device__ __forceinline__ float4 lds128v(uint32_t addr) {
    float4 r;
    asm volatile("ld.shared.v4.f32 {%0,%1,%2,%3}, [%4];"
                 : "=f"(r.x), "=f"(r.y), "=f"(r.z), "=f"(r.w) : "r"(addr));
    return r;
}

// 8-value butterfly transpose-reduce. In: wv[0..7] per lane. Out: return on
// lane l == full 32-lane sum of value (l & 7). (R10/R13-proven.)
__device__ __forceinline__ float butterfly8(float wv[8], int lane) {
#pragma unroll
    for (int step = 0; step < 3; step++) {
        const int off = 4 >> step;
        const bool up = (lane & off) != 0;
#pragma unroll
        for (int i = 0; i < 4; i++) {
            if (i < (4 >> step)) {
                const float send = up ? wv[i] : wv[i + (4 >> step)];
                const float recv = __shfl_xor_sync(0xffffffffu, send, off);
                wv[i] = (up ? wv[i + (4 >> step)] : wv[i]) + recv;
            }
        }
    }
    float s = wv[0];
    s += __shfl_xor_sync(0xffffffffu, s, 8);
    s += __shfl_xor_sync(0xffffffffu, s, 16);
    return s;
}

// ---------------------------------------------------------------------------
// Pass 1 = EXACT R13 hot loop (best measured: row-list compaction, q in smem
// via volatile LDS, xv in registers, dual butterfly8, SCALAR accumulate —
// FFMA2 variants regressed in R8/R12/R15 and are abandoned), plus a fused
// combine tail: the last block per batch (fence+atomic-counter election,
// threadFenceReduction pattern) sums the 16 chunk partials, normalizes, and
// writes g_pooled — replacing the separate pool_combine launch. The elected
// block resets its counter, so every run leaves g_cnt[] at 0 (graph-replay
// deterministic).
// exp(-1e9)==0 in fp32 => skipping masked rows is exact; |score|<~4 => no
// max subtraction needed.
// ---------------------------------------------------------------------------
__global__ void __launch_bounds__(128, 8)
pool_pass1(const float* __restrict__ x,
           const int* __restrict__ mask,   // bool coerced to int32 by harness
           const float* __restrict__ q)
{
    const int blk  = blockIdx.x;
    const int b    = blk / CHUNKS;
    const int c    = blk % CHUNKS;
    const int w    = threadIdx.x >> 5;
    const int lane = threadIdx.x & 31;

    __shared__ float4 qS[H_][32];           // query chunks, lane-strided
    __shared__ float  sP[WARPS][2][16];     // double-buffered weight broadcast
    __shared__ float  sAcc[WARPS][KD_ * H_];
    __shared__ float  sZ[WARPS][H_];
    __shared__ int    rowsS[WARPS][ROWS_PER_WARP + 4];
    __shared__ bool   isLast;
    __shared__ float  Zs[H_];

    // qS[h][lane] = floats [lane*4, lane*4+4) of head h's query (w == h)
    qS[w][lane] = *reinterpret_cast<const float4*>(q + w * KD_ + lane * 4);

    // ---- build this warp's live-row list (once) ----
    const int l0 = c * (L_ / CHUNKS) + w * ROWS_PER_WARP;
    const int* mb = mask + (size_t)b * L_ + l0;
    int cnt = 0;
#pragma unroll
    for (int half = 0; half < 2; half++) {
        const unsigned mm = __ballot_sync(0xffffffffu, mb[half * 32 + lane] != 0);
        const int rank = __popc(mm & ((1u << lane) - 1));
        if ((mm >> lane) & 1u) rowsS[w][cnt + rank] = half * 32 + lane;
        cnt += __popc(mm);
    }
    if (lane < 4) rowsS[w][cnt + lane] = 0;   // pad (zero-weighted later)
    __syncthreads();                          // qS visible to all warps

    float acc[4][H_];
#pragma unroll
    for (int j = 0; j < 4; j++)
#pragma unroll
        for (int h = 0; h < H_; h++) acc[j][h] = 0.0f;
    float zaccA = 0.0f, zaccB = 0.0f;

    const char* baseL = (const char*)(x + (size_t)b * L_ * KD_ + (size_t)l0 * KD_)
                        + lane * 16;
    const uint32_t qAddr = smem_u32(&qS[0][lane]);   // +512*h per head
    const int myrow = (lane & 7) >> 1;

    int pb = 0;
#pragma unroll 1
    for (int base = 0; base < cnt; base += 4) {
        const float keep = (base + myrow < cnt) ? 1.0f : 0.0f;

        int r[4];
#pragma unroll
        for (int i = 0; i < 4; i++) r[i] = rowsS[w][base + i];   // LDS broadcast

        float4 xv[4];
#pragma unroll
        for (int i = 0; i < 4; i++)
            xv[i] = *reinterpret_cast<const float4*>(baseL + ((unsigned)r[i] << 9));

        // ---- batch A: heads 0,1 -> wv[row*2 + hh] ----
        float wv[8];
        {
            const float4 qa = lds128v(qAddr);
            const float4 qb = lds128v(qAddr + 512);
#pragma unroll
            for (int i = 0; i < 4; i++) {
                wv[i * 2 + 0] = xv[i].x * qa.x + xv[i].y * qa.y
                              + xv[i].z * qa.z + xv[i].w * qa.w;
                wv[i * 2 + 1] = xv[i].x * qb.x + xv[i].y * qb.y
                              + xv[i].z * qb.z + xv[i].w * qb.w;
            }
        }
        float eA = __expf(butterfly8(wv, lane)) * keep;

        // ---- batch B: heads 2,3 ----
        {
            const float4 qc = lds128v(qAddr + 1024);
            const float4 qd = lds128v(qAddr + 1536);
#pragma unroll
            for (int i = 0; i < 4; i++) {
                wv[i * 2 + 0] = xv[i].x * qc.x + xv[i].y * qc.y
                              + xv[i].z * qc.z + xv[i].w * qc.w;
                wv[i * 2 + 1] = xv[i].x * qd.x + xv[i].y * qd.y
                              + xv[i].z * qd.z + xv[i].w * qd.w;
            }
        }
        float eB = __expf(butterfly8(wv, lane)) * keep;

        // ---- broadcast weights: lanes 0..7 carry the distinct values ----
        if (lane < 8) {
            const int row = lane >> 1, hh = lane & 1;
            sP[w][pb][row * 4 + hh]     = eA;   // heads 0,1
            sP[w][pb][row * 4 + 2 + hh] = eB;   // heads 2,3
        } else {
            eA = 0.0f; eB = 0.0f;
        }
        __syncwarp();
        zaccA += eA;                    // Z[lane&1]     partial
        zaccB += eB;                    // Z[2+(lane&1)] partial

        // ---- accumulate 4 rows (xv in registers, scalar FMA) ----
#pragma unroll
        for (int i = 0; i < 4; i++) {
            const float4 pv = *reinterpret_cast<const float4*>(&sP[w][pb][i * 4]);
            acc[0][0] = fmaf(xv[i].x, pv.x, acc[0][0]);
            acc[0][1] = fmaf(xv[i].x, pv.y, acc[0][1]);
            acc[0][2] = fmaf(xv[i].x, pv.z, acc[0][2]);
            acc[0][3] = fmaf(xv[i].x, pv.w, acc[0][3]);
            acc[1][0] = fmaf(xv[i].y, pv.x, acc[1][0]);
            acc[1][1] = fmaf(xv[i].y, pv.y, acc[1][1]);
            acc[1][2] = fmaf(xv[i].y, pv.z, acc[1][2]);
            acc[1][3] = fmaf(xv[i].y, pv.w, acc[1][3]);
            acc[2][0] = fmaf(xv[i].z, pv.x, acc[2][0]);
            acc[2][1] = fmaf(xv[i].z, pv.y, acc[2][1]);
            acc[2][2] = fmaf(xv[i].z, pv.z, acc[2][2]);
            acc[2][3] = fmaf(xv[i].z, pv.w, acc[2][3]);
            acc[3][0] = fmaf(xv[i].w, pv.x, acc[3][0]);
            acc[3][1] = fmaf(xv[i].w, pv.y, acc[3][1]);
            acc[3][2] = fmaf(xv[i].w, pv.z, acc[3][2]);
            acc[3][3] = fmaf(xv[i].w, pv.w, acc[3][3]);
        }
        pb ^= 1;                       // next iter writes other sP buffer; its
                                       // syncwarp fences reuse of this one.
    }

    // Z reduce: same-parity lanes -> lanes 0,1 hold (Z0,Z1) and (Z2,Z3)
    float zA = zaccA, zB = zaccB;
#pragma unroll
    for (int off = 16; off >= 2; off >>= 1) {
        zA += __shfl_xor_sync(0xffffffffu, zA, off);
        zB += __shfl_xor_sync(0xffffffffu, zB, off);
    }

    // ---- block-level deterministic reduce ----
#pragma unroll
    for (int j = 0; j < 4; j++)
#pragma unroll
        for (int h = 0; h < H_; h++)
            sAcc[w][(lane * 4 + j) * H_ + h] = acc[j][h];   // idx = k*H + h
    if (lane < 2) {
        sZ[w][lane]     = zA;
        sZ[w][2 + lane] = zB;
    }
    __syncthreads();

    for (int idx = threadIdx.x; idx < KD_ * H_; idx += 128) {
        float vv = 0.f;
#pragma unroll
        for (int ww = 0; ww < WARPS; ww++) vv += sAcc[ww][idx];
        g_pacc[blk][idx] = vv;
    }
    if (threadIdx.x < H_) {
        float vv = 0.f;
#pragma unroll
        for (int ww = 0; ww < WARPS; ww++) vv += sZ[ww][threadIdx.x];
        g_pZ[blk][threadIdx.x] = vv;
    }

    // ---- fused combine: last block per batch does the chunk reduction ----
    if (threadIdx.x == 0) {
        __threadfence();                         // publish g_pacc/g_pZ writes
        const int t = atomicAdd(&g_cnt[b], 1);
        isLast = (t == CHUNKS - 1);
        if (isLast) g_cnt[b] = 0;                // restore invariant for replay
    }
    __syncthreads();
    if (!isLast) return;

    // All 16 chunks of batch b are published (fence-before-atomic by each).
    if (threadIdx.x < H_) {
        float vv = 0.f;
#pragma unroll
        for (int cc = 0; cc < CHUNKS; cc++) vv += g_pZ[b * CHUNKS + cc][threadIdx.x];
        Zs[threadIdx.x] = vv;
    }
    __syncthreads();
#pragma unroll
    for (int e = 0; e < 4; e++) {
        const int idx = threadIdx.x + e * 128;   // coalesced
        float vv = 0.f;
#pragma unroll
        for (int cc = 0; cc < CHUNKS; cc++) vv += g_pacc[b * CHUNKS + cc][idx];
        g_pooled[b][idx] = vv / Zs[idx & (H_ - 1)];
    }
}

// ---------------------------------------------------------------------------
// Pass 2 (R13-proven): out = relu(pooled @ W^T + b + relu(emb[num])).
// Grid = B * 8 (batch x 32-output group); warp computes 4 outputs.
// ---------------------------------------------------------------------------
__global__ void __launch_bounds__(256, 4)
pool_gemv(const float* __restrict__ W,
          const float* __restrict__ bias,
          const float* __restrict__ emb,
          const int* __restrict__ num,
          float* __restrict__ out)
{
    const int b    = blockIdx.x >> 3;
    const int og   = blockIdx.x & 7;
    const int tid  = threadIdx.x;
    const int wrp  = tid >> 5;
    const int lane = tid & 31;
    const int o0   = og * 32 + wrp * 4;

    __shared__ float pooled[KD_ * H_];
    for (int idx = tid; idx < (KD_ * H_) / 4; idx += 256)
        reinterpret_cast<float4*>(pooled)[idx] =
            reinterpret_cast<const float4*>(g_pooled[b])[idx];
    __syncthreads();

    float4 pv[4];
#pragma unroll
    for (int qi = 0; qi < 4; qi++)
        pv[qi] = *reinterpret_cast<const float4*>(&pooled[qi * 128 + lane * 4]);

    float a[4];
#pragma unroll
    for (int j = 0; j < 4; j++) {
        const float* Wr = W + (size_t)(o0 + j) * (KD_ * H_);
        float ssum = 0.f;
#pragma unroll
        for (int qi = 0; qi < 4; qi++) {
            const float4 wv = *reinterpret_cast<const float4*>(Wr + qi * 128 + lane * 4);
            ssum = fmaf(wv.x, pv[qi].x, fmaf(wv.y, pv[qi].y,
                   fmaf(wv.z, pv[qi].z, fmaf(wv.w, pv[qi].w, ssum))));
        }
        a[j] = warp_sum32(ssum);
    }

    if (lane == 0) {
        const int nb = num[b];
#pragma unroll
        for (int j = 0; j < 4; j++) {
            const int o = o0 + j;
            float vv = a[j] + bias[o] + fmaxf(emb[(size_t)nb * OUT_ + o], 0.f);
            out[(size_t)b * OUT_ + o] = fmaxf(vv, 0.f);
        }
    }
}

// ---------------------------------------------------------------------------
// Launch.  Inputs (metadata order): x, mask, num, queries, W, b, emb
// ---------------------------------------------------------------------------
extern "C" void kernel_launch(void* const* d_in, const int* in_sizes, int n_in,
                              void* d_out, int out_size)
{
    const float* x    = (const float*)d_in[0];
    const int*   mask = (const int*)d_in[1];     // bool -> int32 on upload
    const int*   num  = (const int*)d_in[2];
    const float* q    = (const float*)d_in[3];
    const float* W    = (const float*)d_in[4];
    const float* bias = (const float*)d_in[5];
    const float* emb  = (const float*)d_in[6];
    float*       out  = (float*)d_out;

    pool_pass1<<<NBLK1, 128>>>(x, mask, q);
    pool_gemv<<<B_ * 8, 256>>>(W, bias, emb, num, out);
}